// round 5
// baseline (speedup 1.0000x reference)
#include <cuda_runtime.h>

// Fixed shapes for CIFAR10Net_86096914416128
#define TT    16
#define NB    32
#define CIN   3
#define HH    32
#define WWID  32
#define COUT  128
#define KW27  27

// smem tile (u64 units): [t8][cin3][row4][cols], colmap-padded rows
#define ROWS4   4
#define RSTRIDE 38                    // 34 cols + 2x2 gap -> 304B, 16B-aligned rows
#define CSTRIDE (ROWS4 * RSTRIDE)     // 152 per cin
#define TSTRIDE (CIN * CSTRIDE)       // 456 per time step
#define TCHUNK  8                     // timesteps staged per phase
#define NPAIRS_T (CIN * ROWS4 * 34)   // 408 logical pairs per t

typedef unsigned long long u64;

__device__ float g_w[COUT * KW27];

// ---------- packed f32x2 helpers ----------
__device__ __forceinline__ u64 pack2(float a, float b) {
    u64 r; asm("mov.b64 %0,{%1,%2};" : "=l"(r) : "f"(a), "f"(b)); return r;
}
__device__ __forceinline__ void unpack2(u64 v, float& a, float& b) {
    asm("mov.b64 {%0,%1},%2;" : "=f"(a), "=f"(b) : "l"(v));
}
__device__ __forceinline__ u64 ffma2(u64 a, u64 b, u64 c) {
    asm("fma.rn.f32x2 %0,%1,%2,%0;" : "+l"(c) : "l"(a), "l"(b)); return c;
}
__device__ __forceinline__ u64 fadd2(u64 a, u64 b) {
    u64 r; asm("add.rn.f32x2 %0,%1,%2;" : "=l"(r) : "l"(a), "l"(b)); return r;
}
__device__ __forceinline__ u64 fmul2(u64 a, u64 b) {
    u64 r; asm("mul.rn.f32x2 %0,%1,%2;" : "=l"(r) : "l"(a), "l"(b)); return r;
}

// conflict-free column map: 16B gap every 16 cols (keeps 16B chunk starts even)
__device__ __forceinline__ int colmap(int c) { return c + 2 * (c >> 4); }

// ---------- weight prep: clip + fp32 weight-standardization (matches ref) ----------
__global__ void prep_kernel(const float* __restrict__ w,
                            const float* __restrict__ nw,
                            const float* __restrict__ nb) {
    int c = threadIdx.x;
    if (c >= COUT) return;
    float v[KW27];
    float s = 0.0f;
#pragma unroll
    for (int i = 0; i < KW27; i++) {
        float t = w[c * KW27 + i];
        t = fminf(4.0f, fmaxf(-4.0f, t));
        v[i] = t;
        s = __fadd_rn(s, t);
    }
    float mean = __fdiv_rn(s, 27.0f);
    float ss = 0.0f;
#pragma unroll
    for (int i = 0; i < KW27; i++) {
        float d = __fsub_rn(v[i], mean);
        ss = __fadd_rn(ss, __fmul_rn(d, d));
    }
    float var   = __fdiv_rn(ss, 26.0f);
    float denom = __fsqrt_rn(__fadd_rn(var, 1e-5f));
    float nwc = nw[c];
    float nbc = nb[c];
#pragma unroll
    for (int i = 0; i < KW27; i++) {
        float std = __fdiv_rn(__fsub_rn(v[i], mean), denom);
        g_w[c * KW27 + i] = __fadd_rn(__fmul_rn(std, nwc), nbc);
    }
}

// ---------- fused conv3x3 + LIF scan; f32x2 lanes = 2 output channels ----------
// Grid: 1024 = b(32) * cgroup(2) * row_pair(16). Block: 256 = cp(32) * seg(8).
// Thread: 2 channels (lanes) x 2 rows x 4 cols = 16 outputs.
__global__ void __launch_bounds__(256, 2)
snn_kernel(const float* __restrict__ x,
           const float* __restrict__ thr,
           float* __restrict__ out) {
    __shared__ __align__(16) u64 xs[TCHUNK * TSTRIDE];   // 3648 u64 = 29184 B

    const int tid = threadIdx.x;
    const int bid = blockIdx.x;
    const int bb  = bid >> 5;          // batch
    const int cg  = (bid >> 4) & 1;    // 64-channel group
    const int rs  = bid & 15;          // row-pair
    const int r0  = rs * 2;

    const int cp  = tid >> 3;          // channel pair in group (0..31)
    const int seg = tid & 7;
    const int w0  = seg * 4;
    const int c0  = cg * 64 + cp * 2;
    const int c1  = c0 + 1;

    // weight pairs: lane.x = c0, lane.y = c1
    u64 wp[KW27];
#pragma unroll
    for (int i = 0; i < KW27; i++)
        wp[i] = pack2(g_w[c0 * KW27 + i], g_w[c1 * KW27 + i]);

    const float th0 = thr[c0];
    const float th1 = thr[c1];
    const float CSG = 1.0f - (float)(1.0 / 3.5);
    const u64 C2 = pack2(CSG, CSG);

    const int HW = HH * WWID;

    // LIF state: 2 rows x 4 cols of channel pairs (sm/ss dead in ref scan)
    u64 u0[4]  = {0,0,0,0}, u1[4]  = {0,0,0,0};
    u64 sg0[4] = {0,0,0,0}, sg1[4] = {0,0,0,0};

    const int oo0 = colmap(w0);
    const int oo1 = colmap(w0 + 2);
    const int oo2 = colmap(w0 + 4);

    float* ob = out + ((size_t)bb * COUT + c0) * HW + (size_t)r0 * WWID + w0;
    const size_t ostride = (size_t)NB * COUT * HW;

    for (int h = 0; h < TT / TCHUNK; h++) {
        __syncthreads();   // previous phase's readers done
        // ---- stage TCHUNK timesteps: duplicated scalar pairs (x,x) ----
        for (int idx = tid; idx < TCHUNK * NPAIRS_T; idx += 256) {
            int t    = idx / NPAIRS_T;
            int rem  = idx - t * NPAIRS_T;
            int cin  = rem / (ROWS4 * 34);
            int rem2 = rem - cin * (ROWS4 * 34);
            int j    = rem2 / 34;
            int col  = rem2 - j * 34;
            int gw   = col - 1;
            int gr   = r0 - 1 + j;     // [-1, 32]
            float v = 0.0f;
            if (gw >= 0 && gw < WWID && gr >= 0 && gr < HH)
                v = x[((size_t)((h * TCHUNK + t) * NB + bb) * CIN + cin) * HW + gr * WWID + gw];
            xs[t * TSTRIDE + cin * CSTRIDE + j * RSTRIDE + colmap(col)] = pack2(v, v);
        }
        __syncthreads();

#pragma unroll 2
        for (int t = 0; t < TCHUNK; t++) {
            const u64* tb = xs + t * TSTRIDE;

            u64 acc0[4] = {0,0,0,0};   // output row r0
            u64 acc1[4] = {0,0,0,0};   // output row r0+1
#pragma unroll
            for (int cin = 0; cin < 3; cin++) {
#pragma unroll
                for (int j = 0; j < 4; j++) {      // tile row = r0-1+j
                    const u64* rowp = tb + cin * CSTRIDE + j * RSTRIDE;
                    ulonglong2 p0 = *reinterpret_cast<const ulonglong2*>(rowp + oo0);
                    ulonglong2 p1 = *reinterpret_cast<const ulonglong2*>(rowp + oo1);
                    ulonglong2 p2 = *reinterpret_cast<const ulonglong2*>(rowp + oo2);
                    u64 xr[6] = {p0.x, p0.y, p1.x, p1.y, p2.x, p2.y};
                    if (j < 3) {                   // kh = j for row r0
                        const int wb = (cin * 3 + j) * 3;
#pragma unroll
                        for (int kw = 0; kw < 3; kw++) {
                            const u64 wv = wp[wb + kw];
#pragma unroll
                            for (int ww = 0; ww < 4; ww++)
                                acc0[ww] = ffma2(wv, xr[ww + kw], acc0[ww]);
                        }
                    }
                    if (j >= 1) {                  // kh = j-1 for row r0+1
                        const int wb = (cin * 3 + (j - 1)) * 3;
#pragma unroll
                        for (int kw = 0; kw < 3; kw++) {
                            const u64 wv = wp[wb + kw];
#pragma unroll
                            for (int ww = 0; ww < 4; ww++)
                                acc1[ww] = ffma2(wv, xr[ww + kw], acc1[ww]);
                        }
                    }
                }
            }

            // LIF update + spike/reset for both rows; split lanes into channels
            float a0[4], a1[4], b0[4], b1[4];   // a* = channel c0, b* = channel c1
#pragma unroll
            for (int k = 0; k < 4; k++) {
                u64 s  = fmul2(fadd2(sg0[k], acc0[k]), C2);
                u64 uu = fadd2(u0[k], s);
                float ux, uy, sx, sy;
                unpack2(uu, ux, uy);
                unpack2(s,  sx, sy);
                a0[k] = (ux >= th0) ? 1.0f : 0.0f;
                b0[k] = (uy >= th1) ? 1.0f : 0.0f;
                if (ux >= th0) { ux = 0.0f; sx = 0.0f; }
                if (uy >= th1) { uy = 0.0f; sy = 0.0f; }
                u0[k]  = pack2(ux, uy);
                sg0[k] = pack2(sx, sy);

                s  = fmul2(fadd2(sg1[k], acc1[k]), C2);
                uu = fadd2(u1[k], s);
                unpack2(uu, ux, uy);
                unpack2(s,  sx, sy);
                a1[k] = (ux >= th0) ? 1.0f : 0.0f;
                b1[k] = (uy >= th1) ? 1.0f : 0.0f;
                if (ux >= th0) { ux = 0.0f; sx = 0.0f; }
                if (uy >= th1) { uy = 0.0f; sy = 0.0f; }
                u1[k]  = pack2(ux, uy);
                sg1[k] = pack2(sx, sy);
            }
            float* op = ob + (size_t)(h * TCHUNK + t) * ostride;
            *reinterpret_cast<float4*>(op)             = make_float4(a0[0], a0[1], a0[2], a0[3]);
            *reinterpret_cast<float4*>(op + WWID)      = make_float4(a1[0], a1[1], a1[2], a1[3]);
            *reinterpret_cast<float4*>(op + HW)        = make_float4(b0[0], b0[1], b0[2], b0[3]);
            *reinterpret_cast<float4*>(op + HW + WWID) = make_float4(b1[0], b1[1], b1[2], b1[3]);
        }
    }
}

extern "C" void kernel_launch(void* const* d_in, const int* in_sizes, int n_in,
                              void* d_out, int out_size) {
    const float* x  = (const float*)d_in[0];   // [16,32,3,32,32]
    const float* w  = (const float*)d_in[1];   // [128,3,3,3]
    const float* nw = (const float*)d_in[2];   // [128]
    const float* nb = (const float*)d_in[3];   // [128]
    const float* th = (const float*)d_in[4];   // [128]
    float* out = (float*)d_out;                // [16,32,128,32,32]

    prep_kernel<<<1, 128>>>(w, nw, nb);
    snn_kernel<<<1024, 256>>>(x, th, out);
}